// round 12
// baseline (speedup 1.0000x reference)
#include <cuda_runtime.h>
#include <cuda_fp16.h>
#include <cstdint>

// ParallelEmbedding: out[t,:] = W[x[t],:] + A[x[t],:] @ B
// NT=16384, DIM=1024, RANK=256.
// fp16 mma.sync GEMM, fp32 accum SEEDED with gathered W rows (epilogue = pure
// stores). Double-buffered SMEM, register-prefetched A gather, streaming
// cache hints on W/out.

#define NT    16384
#define DIM   1024
#define RANK  256
#define BM    128
#define BN    128
#define KCH   64
#define NCHUNK (RANK / KCH)

#define SMEM_TOKS 0
#define SMEM_AH   1024
#define SMEM_BH   17408
#define BUF_STRIDE 32768
#define SMEM_TOTAL 66560

#define SW128(off) ((off) ^ (((off) >> 3) & 0x70))

__device__ __half g_BT[DIM * RANK];   // B^T fp16, [DIM][RANK] row-major

__device__ __forceinline__ uint32_t smem_u32(const void* p) {
    uint32_t a;
    asm("{ .reg .u64 t; cvta.to.shared.u64 t, %1; cvt.u32.u64 %0, t; }"
        : "=r"(a) : "l"(p));
    return a;
}
__device__ __forceinline__ void ldsm4(uint32_t* r, uint32_t addr) {
    asm volatile("ldmatrix.sync.aligned.m8n8.x4.shared.b16 {%0,%1,%2,%3}, [%4];"
                 : "=r"(r[0]), "=r"(r[1]), "=r"(r[2]), "=r"(r[3]) : "r"(addr));
}
__device__ __forceinline__ void mma_fp16(float* c, const uint32_t* a,
                                         const uint32_t* b) {
    asm volatile(
        "mma.sync.aligned.m16n8k16.row.col.f32.f16.f16.f32 "
        "{%0,%1,%2,%3}, {%4,%5,%6,%7}, {%8,%9}, {%0,%1,%2,%3};"
        : "+f"(c[0]), "+f"(c[1]), "+f"(c[2]), "+f"(c[3])
        : "r"(a[0]), "r"(a[1]), "r"(a[2]), "r"(a[3]), "r"(b[0]), "r"(b[1]));
}
__device__ __forceinline__ uint32_t packh(float a, float b) {
    __half2 t = __halves2half2(__float2half(a), __float2half(b));
    return *reinterpret_cast<uint32_t*>(&t);
}

// ---------------- Prep: B[K][N] fp32 -> B^T fp16 [N][K] ----------------
__global__ void prep_B_kernel(const float* __restrict__ B) {
    __shared__ float tile[32][33];
    const int tx = threadIdx.x & 31;
    const int ty = threadIdx.x >> 5;
    const int k0 = blockIdx.x * 32;
    const int n0 = blockIdx.y * 32;
    #pragma unroll
    for (int i = 0; i < 4; ++i)
        tile[ty + 8 * i][tx] = B[(size_t)(k0 + ty + 8 * i) * DIM + n0 + tx];
    __syncthreads();
    #pragma unroll
    for (int i = 0; i < 4; ++i) {
        int nl = ty + 8 * i;
        g_BT[(size_t)(n0 + nl) * RANK + k0 + tx] = __float2half(tile[tx][nl]);
    }
}

// ---------------- Main kernel ----------------
__global__ __launch_bounds__(256, 2)
void lora_embed_hmma_kernel(const int*   __restrict__ x,
                            const float* __restrict__ W,
                            const float* __restrict__ A,
                            float*       __restrict__ out)
{
    extern __shared__ char smem[];
    const uint32_t sb  = smem_u32(smem);
    const int tid = threadIdx.x;
    const int wid = tid >> 5;
    const int lid = tid & 31;
    const int wm  = wid >> 1;                 // 0..3 : 32 rows each
    const int wn  = wid & 1;                  // 0..1 : 64 cols each
    const int m0  = blockIdx.x * BM;
    const int n0  = blockIdx.y * BN;

    int* toks = reinterpret_cast<int*>(smem + SMEM_TOKS);
    if (tid < BM) toks[tid] = x[m0 + tid];
    __syncthreads();

    // --- Seed accumulators with gathered W fragments (c-frag layout):
    //     row = wm*32 + mf*16 + (lid>>2) + h*8, col = wn*64 + nf*8 + 2*(lid&3).
    //     Issued FIRST so the DRAM latency overlaps the chunk-0 staging below.
    float acc[2][8][4];
    const int cl = (lid & 3) * 2;
    #pragma unroll
    for (int mf = 0; mf < 2; ++mf) {
        int rbase = wm * 32 + mf * 16 + (lid >> 2);
        #pragma unroll
        for (int h = 0; h < 2; ++h) {
            const float* wrow =
                W + (size_t)toks[rbase + h * 8] * DIM + n0 + wn * 64 + cl;
            #pragma unroll
            for (int nf = 0; nf < 8; ++nf) {
                float2 wv = __ldcs(reinterpret_cast<const float2*>(wrow + nf * 8));
                acc[mf][nf][2 * h + 0] = wv.x;
                acc[mf][nf][2 * h + 1] = wv.y;
            }
        }
    }

    // --- ldmatrix lane addressing (SW128: kb' = kb ^ (row&7)) ---
    const int t  = lid >> 3;
    const int r8 = lid & 7;
    uint32_t a_rowoff[2], a_xr[2];
    #pragma unroll
    for (int mf = 0; mf < 2; ++mf) {
        int row = wm * 32 + mf * 16 + r8 + (t & 1) * 8;
        a_rowoff[mf] = (uint32_t)row * 128;
        a_xr[mf]     = (uint32_t)(row & 7);
    }
    const int a_kbh = t >> 1;
    uint32_t b_rowoff[4], b_xr[4];
    #pragma unroll
    for (int nfp = 0; nfp < 4; ++nfp) {
        int nrow = wn * 64 + nfp * 16 + (t >> 1) * 8 + r8;
        b_rowoff[nfp] = (uint32_t)nrow * 128;
        b_xr[nfp]     = (uint32_t)(nrow & 7);
    }
    const int b_kbh = t & 1;

    // --- A gather addressing ---
    const int kbf = (tid & 15) << 2;
    const float* aptr[8];
    #pragma unroll
    for (int it = 0; it < 8; ++it) {
        int row = it * 16 + (tid >> 4);
        aptr[it] = A + (size_t)toks[row] * RANK + kbf;
    }

    // --- Prologue: prefetch A chunk 0 ---
    float4 av[8];
    #pragma unroll
    for (int it = 0; it < 8; ++it) av[it] = *reinterpret_cast<const float4*>(aptr[it]);

    for (int c = 0; c < NCHUNK; ++c) {
        const uint32_t bufo = (uint32_t)(c & 1) * BUF_STRIDE;

        // --- STS A (fp32 -> fp16), SW128 ---
        #pragma unroll
        for (int it = 0; it < 8; ++it) {
            int row = it * 16 + (tid >> 4);
            uint32_t off = SW128((uint32_t)(row * 128 + kbf * 2));
            *reinterpret_cast<uint2*>(smem + SMEM_AH + bufo + off) =
                make_uint2(packh(av[it].x, av[it].y), packh(av[it].z, av[it].w));
        }
        // --- Load B chunk c (L2-hot prepped fp16) ---
        {
            const int k0 = c * KCH;
            #pragma unroll
            for (int it = 0; it < 4; ++it) {
                int u = it * 256 + tid;
                int r = u >> 3;
                int j = u & 7;
                size_t src = (size_t)(n0 + r) * RANK + k0 + j * 8;
                *reinterpret_cast<uint4*>(
                    smem + SMEM_BH + bufo + SW128((uint32_t)(r * 128 + j * 16))) =
                    *reinterpret_cast<const uint4*>(g_BT + src);
            }
        }
        __syncthreads();

        // --- Prefetch next A chunk (overlaps MMAs below) ---
        if (c + 1 < NCHUNK) {
            #pragma unroll
            for (int it = 0; it < 8; ++it)
                av[it] = *reinterpret_cast<const float4*>(aptr[it] + (c + 1) * KCH);
        }

        // --- Compute chunk c ---
        #pragma unroll
        for (int ks = 0; ks < 4; ++ks) {
            uint32_t ah[2][4];
            #pragma unroll
            for (int mf = 0; mf < 2; ++mf) {
                uint32_t kb  = (uint32_t)(2 * ks + a_kbh);
                uint32_t off = a_rowoff[mf] + ((kb ^ a_xr[mf]) << 4);
                ldsm4(ah[mf], sb + SMEM_AH + bufo + off);
            }
            #pragma unroll
            for (int nfp = 0; nfp < 4; ++nfp) {
                uint32_t kb  = (uint32_t)(2 * ks + b_kbh);
                uint32_t off = b_rowoff[nfp] + ((kb ^ b_xr[nfp]) << 4);
                uint32_t bh[4];
                ldsm4(bh, sb + SMEM_BH + bufo + off);
                #pragma unroll
                for (int h = 0; h < 2; ++h) {
                    int nf = nfp * 2 + h;
                    mma_fp16(acc[0][nf], ah[0], bh + 2 * h);
                    mma_fp16(acc[1][nf], ah[1], bh + 2 * h);
                }
            }
        }
        // Buffer alternation makes one sync per chunk sufficient.
    }

    // --- Epilogue: pure streaming stores ---
    #pragma unroll
    for (int mf = 0; mf < 2; ++mf) {
        int rbase = wm * 32 + mf * 16 + (lid >> 2);
        #pragma unroll
        for (int h = 0; h < 2; ++h) {
            int row = rbase + h * 8;
            float* orow = out + (size_t)(m0 + row) * DIM + n0 + wn * 64 + cl;
            #pragma unroll
            for (int nf = 0; nf < 8; ++nf) {
                float2 ov;
                ov.x = acc[mf][nf][2 * h + 0];
                ov.y = acc[mf][nf][2 * h + 1];
                __stcs(reinterpret_cast<float2*>(orow + nf * 8), ov);
            }
        }
    }
}

extern "C" void kernel_launch(void* const* d_in, const int* in_sizes, int n_in,
                              void* d_out, int out_size) {
    const int*   x = (const int*)  d_in[0];
    const float* W = (const float*)d_in[1];
    const float* A = (const float*)d_in[2];
    const float* B = (const float*)d_in[3];
    float* out = (float*)d_out;

    (void)cudaFuncSetAttribute(lora_embed_hmma_kernel,
                               cudaFuncAttributeMaxDynamicSharedMemorySize,
                               SMEM_TOTAL);

    prep_B_kernel<<<dim3(RANK / 32, DIM / 32), 256>>>(B);
    lora_embed_hmma_kernel<<<dim3(NT / BM, DIM / BN), 256, SMEM_TOTAL>>>(x, W, A, out);
}